// round 3
// baseline (speedup 1.0000x reference)
#include <cuda_runtime.h>
#include <cstdint>

// GCN FeatureDiscriminator: B=256, V=512, F=256, O=2
// Kernel A: balanced row-local streaming (graphs 256MB + features 128MB ->
//           bits 8MB, dinv, prescaled sxw).
// Kernel B: per-batch aggregation with packed f32x2 adds + smem transpose-reduce.

#define BATCH 256
#define BV 512
#define BF 256
#define NROWS (BATCH * BV)
#define NTHREADS 512
#define NWARP 16
#define GRID_A 304
#define TOTAL_WARPS_A (GRID_A * NWARP)

__device__ unsigned g_bits[NROWS * 16];   // 8 MB: 512-bit mask per row
__device__ float    g_dinv[NROWS];
__device__ float2   g_sxw[NROWS];         // dinv[w] * (X[w,:] @ W)

// packed fp32x2 helpers
#define ADDX2(out, a, b) asm("add.rn.f32x2 %0, %1, %2;" : "=l"(out) : "l"(a), "l"(b))
#define PADD(acc, cond, val)                                           \
    asm("{\n\t.reg .pred p;\n\tsetp.ne.u32 p, %1, 0;\n\t"              \
        "@p add.rn.f32x2 %0, %0, %2;\n\t}"                             \
        : "+l"(acc) : "r"(cond), "l"(val))
#define UNPACKX2(lo, hi, in) asm("mov.b64 {%0, %1}, %2;" : "=r"(lo), "=r"(hi) : "l"(in))

// ---------------------------------------------------------------------------
// Kernel A: warp per row, grid-stride.
// Bit convention: bits[row][4c+k] bit 'l'  <->  column w = 128*c + 4*l + k
// ---------------------------------------------------------------------------
__global__ __launch_bounds__(NTHREADS, 2)
void gcn_rows_kernel(const float* __restrict__ features,
                     const int*   __restrict__ graphs,
                     const float* __restrict__ conv_weight)   // [F,2] row-major
{
    const int tid  = threadIdx.x;
    const int wid  = tid >> 5;
    const int lane = tid & 31;
    const int gwarp = blockIdx.x * NWARP + wid;

    float w0r[8], w1r[8];
    {
        const float2* cw2 = (const float2*)conv_weight;
        #pragma unroll
        for (int j = 0; j < 8; j++) {
            float2 w = __ldg(cw2 + 8 * lane + j);
            w0r[j] = w.x; w1r[j] = w.y;
        }
    }

    for (int row = gwarp; row < NROWS; row += TOTAL_WARPS_A) {
        const int v = row & (BV - 1);
        const int4*   grow = (const int4*)graphs + (size_t)row * (BV / 4);
        const float4* frow = (const float4*)features + (size_t)row * (BF / 4);

        int4 x0 = __ldcs(grow + 0 * 32 + lane);
        int4 x1 = __ldcs(grow + 1 * 32 + lane);
        int4 x2 = __ldcs(grow + 2 * 32 + lane);
        int4 x3 = __ldcs(grow + 3 * 32 + lane);
        float4 fa = __ldcs(frow + 2 * lane);
        float4 fb = __ldcs(frow + 2 * lane + 1);

        int deg = 0;
        #pragma unroll
        for (int c = 0; c < 4; c++) {
            int4 x = (c == 0) ? x0 : (c == 1) ? x1 : (c == 2) ? x2 : x3;
            int w0 = 128 * c + 4 * lane;
            unsigned m0 = __ballot_sync(0xffffffffu, (x.x != 0) || (w0     == v));
            unsigned m1 = __ballot_sync(0xffffffffu, (x.y != 0) || (w0 + 1 == v));
            unsigned m2 = __ballot_sync(0xffffffffu, (x.z != 0) || (w0 + 2 == v));
            unsigned m3 = __ballot_sync(0xffffffffu, (x.w != 0) || (w0 + 3 == v));
            deg += __popc(m0) + __popc(m1) + __popc(m2) + __popc(m3);
            if (lane == c) {
                ((uint4*)g_bits)[(size_t)row * 4 + c] = make_uint4(m0, m1, m2, m3);
            }
        }

        float acc0 = fa.x * w0r[0];             float acc1 = fa.x * w1r[0];
        acc0 = fmaf(fa.y, w0r[1], acc0);        acc1 = fmaf(fa.y, w1r[1], acc1);
        acc0 = fmaf(fa.z, w0r[2], acc0);        acc1 = fmaf(fa.z, w1r[2], acc1);
        acc0 = fmaf(fa.w, w0r[3], acc0);        acc1 = fmaf(fa.w, w1r[3], acc1);
        acc0 = fmaf(fb.x, w0r[4], acc0);        acc1 = fmaf(fb.x, w1r[4], acc1);
        acc0 = fmaf(fb.y, w0r[5], acc0);        acc1 = fmaf(fb.y, w1r[5], acc1);
        acc0 = fmaf(fb.z, w0r[6], acc0);        acc1 = fmaf(fb.z, w1r[6], acc1);
        acc0 = fmaf(fb.w, w0r[7], acc0);        acc1 = fmaf(fb.w, w1r[7], acc1);
        #pragma unroll
        for (int s = 16; s; s >>= 1) {
            acc0 += __shfl_xor_sync(0xffffffffu, acc0, s);
            acc1 += __shfl_xor_sync(0xffffffffu, acc1, s);
        }
        if (lane == 0) {
            float d = rsqrtf((float)deg);        // deg >= 1 (self-loop)
            g_dinv[row] = d;
            g_sxw[row]  = make_float2(d * acc0, d * acc1);
        }
    }
}

// ---------------------------------------------------------------------------
// Kernel B: per-batch aggregation + head. One CTA per batch, dynamic smem.
// ---------------------------------------------------------------------------
struct SmemB {
    unsigned bits[BV][16];                    // 32 KB
    unsigned long long sxw2[BV];              // 4 KB  packed (s0,s1)
    float dinv[BV];                           // 2 KB
    float2 lw2[BV];                           // 4 KB
    unsigned long long buf[NWARP][8][33];     // 33 KB transpose-reduce buffers
    float wpart[NWARP];
};

__global__ __launch_bounds__(NTHREADS, 2)
void gcn_agg_kernel(const float* __restrict__ conv_bias,
                    const float* __restrict__ lin_weight,   // [2v+o]
                    const float* __restrict__ lin_bias,
                    float* __restrict__ out)
{
    extern __shared__ char smem_raw[];
    SmemB* sm = (SmemB*)smem_raw;

    const int b    = blockIdx.x;
    const int tid  = threadIdx.x;
    const int wid  = tid >> 5;
    const int lane = tid & 31;
    const unsigned lanebit = 1u << lane;

    // ---- stage scratch -> smem (coalesced) ----
    {
        const uint4* src = (const uint4*)g_bits + (size_t)b * (BV * 4);
        uint4* dst = (uint4*)sm->bits;
        #pragma unroll
        for (int i = 0; i < 4; i++) dst[tid + i * NTHREADS] = src[tid + i * NTHREADS];

        sm->sxw2[tid] = ((const unsigned long long*)g_sxw)[b * BV + tid];
        sm->dinv[tid] = g_dinv[b * BV + tid];
        sm->lw2[tid]  = ((const float2*)lin_weight)[tid];
    }
    __syncthreads();

    // preload this lane's fixed 16 packed s-values: w = 128*c + 4*lane + k
    unsigned long long rp[16];
    #pragma unroll
    for (int c = 0; c < 4; c++)
        #pragma unroll
        for (int k = 0; k < 4; k++)
            rp[4 * c + k] = sm->sxw2[128 * c + 4 * lane + k];

    const float cb0 = conv_bias[0];
    const float cb1 = conv_bias[1];

    const int q = lane >> 3;       // 0..3
    const int r = lane & 7;        // 0..7

    float part = 0.0f;
    #pragma unroll
    for (int chunk = 0; chunk < 4; chunk++) {
        const int vbase = wid * 32 + chunk * 8;
        // --- 8 rows of predicated packed accumulation ---
        #pragma unroll
        for (int r8 = 0; r8 < 8; r8++) {
            const uint4* bw = (const uint4*)sm->bits[vbase + r8];
            uint4 q0 = bw[0], q1 = bw[1], q2 = bw[2], q3 = bw[3];
            unsigned long long a0 = 0, a1 = 0, a2 = 0, a3 = 0;
            PADD(a0, q0.x & lanebit, rp[0]);
            PADD(a1, q0.y & lanebit, rp[1]);
            PADD(a2, q0.z & lanebit, rp[2]);
            PADD(a3, q0.w & lanebit, rp[3]);
            PADD(a0, q1.x & lanebit, rp[4]);
            PADD(a1, q1.y & lanebit, rp[5]);
            PADD(a2, q1.z & lanebit, rp[6]);
            PADD(a3, q1.w & lanebit, rp[7]);
            PADD(a0, q2.x & lanebit, rp[8]);
            PADD(a1, q2.y & lanebit, rp[9]);
            PADD(a2, q2.z & lanebit, rp[10]);
            PADD(a3, q2.w & lanebit, rp[11]);
            PADD(a0, q3.x & lanebit, rp[12]);
            PADD(a1, q3.y & lanebit, rp[13]);
            PADD(a2, q3.z & lanebit, rp[14]);
            PADD(a3, q3.w & lanebit, rp[15]);
            ADDX2(a0, a0, a1);
            ADDX2(a2, a2, a3);
            ADDX2(a0, a0, a2);
            sm->buf[wid][r8][lane] = a0;
        }
        __syncwarp();

        // --- transpose-reduce: lane (q,r) sums 8 entries of row r ---
        unsigned long long s = sm->buf[wid][r][8 * q + 0];
        #pragma unroll
        for (int i = 1; i < 8; i++) {
            unsigned long long t = sm->buf[wid][r][8 * q + i];
            ADDX2(s, s, t);
        }
        unsigned lo_u, hi_u;
        UNPACKX2(lo_u, hi_u, s);
        float lo = __uint_as_float(lo_u), hi = __uint_as_float(hi_u);
        lo += __shfl_xor_sync(0xffffffffu, lo, 8);
        hi += __shfl_xor_sync(0xffffffffu, hi, 8);
        lo += __shfl_xor_sync(0xffffffffu, lo, 16);
        hi += __shfl_xor_sync(0xffffffffu, hi, 16);

        // --- epilogue on lanes 0..7 (q == 0): relu + head dot ---
        if (q == 0) {
            const int v = vbase + r;
            float d  = sm->dinv[v];
            float2 lw = sm->lw2[v];
            float h0 = fmaxf(fmaf(d, lo, cb0), 0.0f);
            float h1 = fmaxf(fmaf(d, hi, cb1), 0.0f);
            part = fmaf(h0, lw.x, part);
            part = fmaf(h1, lw.y, part);
        }
        __syncwarp();   // WAR: buf reused next chunk
    }

    // --- final reduce + sigmoid ---
    #pragma unroll
    for (int sh = 16; sh; sh >>= 1) part += __shfl_xor_sync(0xffffffffu, part, sh);
    if (lane == 0) sm->wpart[wid] = part;
    __syncthreads();

    if (wid == 0) {
        float sdot = (lane < NWARP) ? sm->wpart[lane] : 0.0f;
        #pragma unroll
        for (int sh = 8; sh; sh >>= 1) sdot += __shfl_xor_sync(0xffffffffu, sdot, sh);
        if (lane == 0) {
            float logit = sdot + lin_bias[0];
            out[b] = 1.0f / (1.0f + expf(-logit));
        }
    }
}

extern "C" void kernel_launch(void* const* d_in, const int* in_sizes, int n_in,
                              void* d_out, int out_size) {
    const float* features    = (const float*)d_in[0];
    const int*   graphs      = (const int*)  d_in[1];
    const float* conv_weight = (const float*)d_in[2];
    const float* conv_bias   = (const float*)d_in[3];
    const float* lin_weight  = (const float*)d_in[4];
    const float* lin_bias    = (const float*)d_in[5];
    float* out = (float*)d_out;

    static int smem_set = 0;
    if (!smem_set) {
        cudaFuncSetAttribute(gcn_agg_kernel,
                             cudaFuncAttributeMaxDynamicSharedMemorySize,
                             (int)sizeof(SmemB));
        smem_set = 1;
    }

    gcn_rows_kernel<<<GRID_A, NTHREADS>>>(features, graphs, conv_weight);
    gcn_agg_kernel<<<BATCH, NTHREADS, sizeof(SmemB)>>>(conv_bias, lin_weight,
                                                       lin_bias, out);
}